// round 1
// baseline (speedup 1.0000x reference)
#include <cuda_runtime.h>
#include <cuda_bf16.h>
#include <math.h>

// Problem constants
#define BATCH 2
#define SEQ   1024
#define HID   4096
#define NH    32
#define NKV   8
#define HD    128
#define MROWS (BATCH*SEQ)          // 2048
#define GROUPS (NH/NKV)            // 4

// ---------------- scratch (device globals; no cudaMalloc allowed) ----------
__device__ float g_q[(size_t)MROWS * NH * HD];     // [B,S,NH,HD]   33.5 MB
__device__ float g_k[(size_t)MROWS * NKV * HD];    // [B,S,NKV,HD]   8.4 MB
__device__ float g_v[(size_t)MROWS * NKV * HD];    // [B,S,NKV,HD]   8.4 MB
__device__ float g_attn[(size_t)MROWS * NH * HD];  // [B,S,NH,HD]   33.5 MB

// ---------------- SGEMM: C[M,N] = A[M,K] @ B[K,N], all row-major -----------
// 128x128 tile, BK=16, 256 threads, 8x8 per-thread micro-tile.
#define GBM 128
#define GBN 128
#define GBK 16

__global__ __launch_bounds__(256) void sgemm_kernel(
    const float* __restrict__ A, const float* __restrict__ B,
    float* __restrict__ C, int M, int N, int K)
{
    __shared__ float As[GBK][GBM];        // transposed A tile
    __shared__ float Bs[GBK][GBN];

    const int tid = threadIdx.x;
    const int row0 = blockIdx.y * GBM;
    const int col0 = blockIdx.x * GBN;
    const int tx = tid & 15;              // 0..15 -> 8 cols each
    const int ty = tid >> 4;              // 0..15 -> 8 rows each

    float acc[8][8];
    #pragma unroll
    for (int i = 0; i < 8; i++)
        #pragma unroll
        for (int j = 0; j < 8; j++) acc[i][j] = 0.f;

    for (int k0 = 0; k0 < K; k0 += GBK) {
        // Load A tile (128x16) and B tile (16x128), 2 float4 each per thread
        #pragma unroll
        for (int it = 0; it < 2; it++) {
            int f = tid * 2 + it;                 // 0..511
            int ar = f >> 2, ak = (f & 3) << 2;   // A: row 0..127, k 0,4,8,12
            float4 av = *(const float4*)&A[(size_t)(row0 + ar) * K + k0 + ak];
            As[ak + 0][ar] = av.x;
            As[ak + 1][ar] = av.y;
            As[ak + 2][ar] = av.z;
            As[ak + 3][ar] = av.w;
            int br = f >> 5, bc = (f & 31) << 2;  // B: k 0..15, col 0..124
            float4 bv = *(const float4*)&B[(size_t)(k0 + br) * N + col0 + bc];
            *(float4*)&Bs[br][bc] = bv;
        }
        __syncthreads();

        #pragma unroll
        for (int kk = 0; kk < GBK; kk++) {
            float ar[8], br[8];
            *(float4*)&ar[0] = *(const float4*)&As[kk][ty * 8];
            *(float4*)&ar[4] = *(const float4*)&As[kk][ty * 8 + 4];
            *(float4*)&br[0] = *(const float4*)&Bs[kk][tx * 8];
            *(float4*)&br[4] = *(const float4*)&Bs[kk][tx * 8 + 4];
            #pragma unroll
            for (int i = 0; i < 8; i++)
                #pragma unroll
                for (int j = 0; j < 8; j++)
                    acc[i][j] += ar[i] * br[j];
        }
        __syncthreads();
    }

    #pragma unroll
    for (int i = 0; i < 8; i++) {
        size_t crow = (size_t)(row0 + ty * 8 + i) * N + col0 + tx * 8;
        float4 v0 = {acc[i][0], acc[i][1], acc[i][2], acc[i][3]};
        float4 v1 = {acc[i][4], acc[i][5], acc[i][6], acc[i][7]};
        *(float4*)&C[crow]     = v0;
        *(float4*)&C[crow + 4] = v1;
    }
}

// ---------------- RoPE (in-place) ------------------------------------------
// t layout [B,S,nheads,128]; pairs (d, d+64), cos/sin [S,64]
__global__ void rope_kernel(float* __restrict__ t,
                            const float* __restrict__ fcos,
                            const float* __restrict__ fsin,
                            int nheads, int total_pairs)
{
    int idx = blockIdx.x * blockDim.x + threadIdx.x;
    if (idx >= total_pairs) return;
    int d = idx & 63;
    int row = idx >> 6;                   // (b*S + s)*nheads + h
    int s = (row / nheads) % SEQ;
    size_t base = (size_t)row * HD;
    float c  = fcos[s * 64 + d];
    float sn = fsin[s * 64 + d];
    float t1 = t[base + d];
    float t2 = t[base + 64 + d];
    t[base + d]      = t1 * c  - t2 * sn;
    t[base + 64 + d] = t1 * sn + t2 * c;
}

// ---------------- Flash attention (causal, GQA) -----------------------------
// Grid: (S/64, NH, B). Block: 256 threads. Dynamic smem ~113 KB.
#define BQ 64
#define BKT 64
#define PS_STRIDE 65   // padded to avoid bank conflicts in row softmax

__global__ __launch_bounds__(256) void flash_attn_kernel(
    const float* __restrict__ Q, const float* __restrict__ K,
    const float* __restrict__ V, float* __restrict__ O)
{
    extern __shared__ float sm[];
    float* Qt  = sm;                     // [HD][BQ]  transposed
    float* Kt  = Qt + HD * BQ;           // [HD][BKT] transposed
    float* Vs  = Kt + HD * BKT;          // [BKT][HD]
    float* Ps  = Vs + BKT * HD;          // [BQ][PS_STRIDE]
    float* m_s = Ps + BQ * PS_STRIDE;    // [BQ]
    float* l_s = m_s + BQ;               // [BQ]
    float* e_s = l_s + BQ;               // [BQ]

    const int qb = blockIdx.x;
    const int h  = blockIdx.y;
    const int b  = blockIdx.z;
    const int kvh = h / GROUPS;
    const int tid = threadIdx.x;
    const int tx = tid & 15;             // k / out-col direction
    const int ty = tid >> 4;             // q direction

    const float scale = 0.08838834764831845f;  // 1/sqrt(128)

    // Load Q tile transposed: Qt[d][q]
    const float* Qg = Q + ((size_t)(b * SEQ + qb * BQ) * NH + h) * HD;
    for (int f = tid; f < BQ * HD / 4; f += 256) {
        int q = f >> 5;                  // 0..63
        int d4 = (f & 31) << 2;          // 0,4,...,124
        float4 v = *(const float4*)(Qg + (size_t)q * NH * HD + d4);
        Qt[(d4 + 0) * BQ + q] = v.x;
        Qt[(d4 + 1) * BQ + q] = v.y;
        Qt[(d4 + 2) * BQ + q] = v.z;
        Qt[(d4 + 3) * BQ + q] = v.w;
    }
    if (tid < BQ) { m_s[tid] = -1e30f; l_s[tid] = 0.f; }

    float acc[4][8];
    #pragma unroll
    for (int i = 0; i < 4; i++)
        #pragma unroll
        for (int j = 0; j < 8; j++) acc[i][j] = 0.f;

    const int nkt = qb + 1;  // causal: only tiles with k0 <= q0
    for (int kt = 0; kt < nkt; kt++) {
        __syncthreads();
        // Load K (transposed) and V tiles
        const float* Kg = K + ((size_t)(b * SEQ + kt * BKT) * NKV + kvh) * HD;
        const float* Vg = V + ((size_t)(b * SEQ + kt * BKT) * NKV + kvh) * HD;
        for (int f = tid; f < BKT * HD / 4; f += 256) {
            int k = f >> 5;
            int d4 = (f & 31) << 2;
            float4 kv = *(const float4*)(Kg + (size_t)k * NKV * HD + d4);
            Kt[(d4 + 0) * BKT + k] = kv.x;
            Kt[(d4 + 1) * BKT + k] = kv.y;
            Kt[(d4 + 2) * BKT + k] = kv.z;
            Kt[(d4 + 3) * BKT + k] = kv.w;
            float4 vv = *(const float4*)(Vg + (size_t)k * NKV * HD + d4);
            *(float4*)(Vs + (size_t)k * HD + d4) = vv;
        }
        __syncthreads();

        // Scores: thread computes S[ty*4+i][tx*4+j]
        float s[4][4];
        #pragma unroll
        for (int i = 0; i < 4; i++)
            #pragma unroll
            for (int j = 0; j < 4; j++) s[i][j] = 0.f;

        #pragma unroll 4
        for (int d = 0; d < HD; d++) {
            float qv[4], kv[4];
            *(float4*)qv = *(const float4*)(Qt + d * BQ + ty * 4);
            *(float4*)kv = *(const float4*)(Kt + d * BKT + tx * 4);
            #pragma unroll
            for (int i = 0; i < 4; i++)
                #pragma unroll
                for (int j = 0; j < 4; j++)
                    s[i][j] += qv[i] * kv[j];
        }

        // Write scaled + masked scores to Ps
        const int k0 = kt * BKT;
        const bool diag = (kt == qb);
        #pragma unroll
        for (int i = 0; i < 4; i++) {
            int qg = qb * BQ + ty * 4 + i;
            #pragma unroll
            for (int j = 0; j < 4; j++) {
                float v = s[i][j] * scale;
                if (diag && (k0 + tx * 4 + j > qg)) v = -1e30f;
                Ps[(ty * 4 + i) * PS_STRIDE + tx * 4 + j] = v;
            }
        }
        __syncthreads();

        // Online softmax, one thread per row (rows padded -> conflict-free)
        if (tid < BQ) {
            float* row = Ps + tid * PS_STRIDE;
            float rmax = row[0];
            #pragma unroll 8
            for (int c = 1; c < BKT; c++) rmax = fmaxf(rmax, row[c]);
            float mnew = fmaxf(m_s[tid], rmax);
            float esc  = __expf(m_s[tid] - mnew);
            float sum = 0.f;
            #pragma unroll 8
            for (int c = 0; c < BKT; c++) {
                float p = __expf(row[c] - mnew);
                row[c] = p;
                sum += p;
            }
            l_s[tid] = l_s[tid] * esc + sum;
            m_s[tid] = mnew;
            e_s[tid] = esc;
        }
        __syncthreads();

        // Rescale accumulators and add P @ V
        float esc_i[4];
        #pragma unroll
        for (int i = 0; i < 4; i++) esc_i[i] = e_s[ty * 4 + i];
        #pragma unroll
        for (int i = 0; i < 4; i++)
            #pragma unroll
            for (int j = 0; j < 8; j++) acc[i][j] *= esc_i[i];

        #pragma unroll 4
        for (int kk = 0; kk < BKT; kk++) {
            float p[4];
            #pragma unroll
            for (int i = 0; i < 4; i++) p[i] = Ps[(ty * 4 + i) * PS_STRIDE + kk];
            float vv[8];
            *(float4*)&vv[0] = *(const float4*)(Vs + (size_t)kk * HD + tx * 8);
            *(float4*)&vv[4] = *(const float4*)(Vs + (size_t)kk * HD + tx * 8 + 4);
            #pragma unroll
            for (int i = 0; i < 4; i++)
                #pragma unroll
                for (int j = 0; j < 8; j++)
                    acc[i][j] += p[i] * vv[j];
        }
    }

    // Normalize and write out
    float* Og = O + ((size_t)(b * SEQ + qb * BQ) * NH + h) * HD;
    #pragma unroll
    for (int i = 0; i < 4; i++) {
        float linv = 1.f / l_s[ty * 4 + i];
        float4 v0 = {acc[i][0] * linv, acc[i][1] * linv,
                     acc[i][2] * linv, acc[i][3] * linv};
        float4 v1 = {acc[i][4] * linv, acc[i][5] * linv,
                     acc[i][6] * linv, acc[i][7] * linv};
        size_t orow = (size_t)(ty * 4 + i) * NH * HD + tx * 8;
        *(float4*)(Og + orow)     = v0;
        *(float4*)(Og + orow + 4) = v1;
    }
}

// ---------------- launch ----------------------------------------------------
static float* sym_addr(const void* sym)
{
    void* p = nullptr;
    cudaGetSymbolAddress(&p, sym);
    return (float*)p;
}

extern "C" void kernel_launch(void* const* d_in, const int* in_sizes, int n_in,
                              void* d_out, int out_size)
{
    const float* x    = (const float*)d_in[0];
    const float* wq   = (const float*)d_in[1];
    const float* wk   = (const float*)d_in[2];
    const float* wv   = (const float*)d_in[3];
    const float* wo   = (const float*)d_in[4];
    const float* fcos = (const float*)d_in[5];
    const float* fsin = (const float*)d_in[6];
    float* out = (float*)d_out;

    float* q    = sym_addr(g_q);
    float* k    = sym_addr(g_k);
    float* v    = sym_addr(g_v);
    float* attn = sym_addr(g_attn);

    // QKV projections
    sgemm_kernel<<<dim3(NH * HD / GBN, MROWS / GBM), 256>>>(x, wq, q, MROWS, NH * HD, HID);
    sgemm_kernel<<<dim3(NKV * HD / GBN, MROWS / GBM), 256>>>(x, wk, k, MROWS, NKV * HD, HID);
    sgemm_kernel<<<dim3(NKV * HD / GBN, MROWS / GBM), 256>>>(x, wv, v, MROWS, NKV * HD, HID);

    // RoPE
    {
        int pq = MROWS * NH * 64;
        int pk = MROWS * NKV * 64;
        rope_kernel<<<(pq + 255) / 256, 256>>>(q, fcos, fsin, NH, pq);
        rope_kernel<<<(pk + 255) / 256, 256>>>(k, fcos, fsin, NKV, pk);
    }

    // Flash attention
    {
        size_t smem = (size_t)(HD * BQ + HD * BKT + BKT * HD
                               + BQ * PS_STRIDE + 3 * BQ) * sizeof(float);
        cudaFuncSetAttribute(flash_attn_kernel,
                             cudaFuncAttributeMaxDynamicSharedMemorySize, (int)smem);
        flash_attn_kernel<<<dim3(SEQ / BQ, NH, BATCH), 256, smem>>>(q, k, v, attn);
    }

    // Output projection
    sgemm_kernel<<<dim3(HID / GBN, MROWS / GBM), 256>>>(attn, wo, out, MROWS, HID, HID);
}

// round 3
// speedup vs baseline: 1.8516x; 1.8516x over previous
#include <cuda_runtime.h>
#include <cuda_bf16.h>
#include <math.h>
#include <stdint.h>

// Problem constants
#define BATCH 2
#define SEQ   1024
#define HID   4096
#define NH    32
#define NKV   8
#define HD    128
#define MROWS (BATCH*SEQ)          // 2048
#define GROUPS (NH/NKV)            // 4

// ======================= warp MMA helpers (sm_80+ path) =====================
__device__ __forceinline__ uint32_t smem_u32(const void* p) {
    uint32_t a;
    asm("{ .reg .u64 t; cvta.to.shared.u64 t, %1; cvt.u32.u64 %0, t; }"
        : "=r"(a) : "l"(p));
    return a;
}

__device__ __forceinline__ void ldsm_x4(uint32_t* r, uint32_t addr) {
    asm volatile("ldmatrix.sync.aligned.m8n8.x4.shared.b16 {%0,%1,%2,%3}, [%4];"
                 : "=r"(r[0]), "=r"(r[1]), "=r"(r[2]), "=r"(r[3]) : "r"(addr));
}

__device__ __forceinline__ void mma16816(float* d, const uint32_t* a,
                                         const uint32_t* b) {
    asm volatile("mma.sync.aligned.m16n8k16.row.col.f32.bf16.bf16.f32 "
                 "{%0,%1,%2,%3}, {%4,%5,%6,%7}, {%8,%9}, {%0,%1,%2,%3};"
                 : "+f"(d[0]), "+f"(d[1]), "+f"(d[2]), "+f"(d[3])
                 : "r"(a[0]), "r"(a[1]), "r"(a[2]), "r"(a[3]),
                   "r"(b[0]), "r"(b[1]));
}

#define CP_ASYNC16(smem, gptr) \
    asm volatile("cp.async.cg.shared.global [%0], [%1], 16;" \
                 :: "r"(smem), "l"(gptr))
#define CP_COMMIT() asm volatile("cp.async.commit_group;" ::: "memory")
#define CP_WAIT(N)  asm volatile("cp.async.wait_group %0;" :: "n"(N) : "memory")

// ---------------- scratch (device globals; no cudaMalloc allowed) ----------
__device__ float g_q[(size_t)MROWS * NH * HD];
__device__ float g_k[(size_t)MROWS * NKV * HD];
__device__ float g_v[(size_t)MROWS * NKV * HD];
__device__ float g_attn[(size_t)MROWS * NH * HD];

__device__ __nv_bfloat16 g_xhi[(size_t)MROWS * HID];
__device__ __nv_bfloat16 g_xlo[(size_t)MROWS * HID];
__device__ __nv_bfloat16 g_ahi[(size_t)MROWS * HID];
__device__ __nv_bfloat16 g_alo[(size_t)MROWS * HID];
__device__ __nv_bfloat16 g_wqhiT[(size_t)HID * HID];
__device__ __nv_bfloat16 g_wqloT[(size_t)HID * HID];
__device__ __nv_bfloat16 g_wkhiT[(size_t)(NKV*HD) * HID];
__device__ __nv_bfloat16 g_wkloT[(size_t)(NKV*HD) * HID];
__device__ __nv_bfloat16 g_wvhiT[(size_t)(NKV*HD) * HID];
__device__ __nv_bfloat16 g_wvloT[(size_t)(NKV*HD) * HID];
__device__ __nv_bfloat16 g_wohiT[(size_t)HID * HID];
__device__ __nv_bfloat16 g_woloT[(size_t)HID * HID];

// ---------------- fp32 -> bf16 hi/lo split (elementwise) --------------------
__global__ void split_kernel(const float4* __restrict__ in,
                             ushort4* __restrict__ hi,
                             ushort4* __restrict__ lo, int n4)
{
    int i = blockIdx.x * blockDim.x + threadIdx.x;
    if (i >= n4) return;
    float4 v = in[i];
    __nv_bfloat16 h0 = __float2bfloat16(v.x);
    __nv_bfloat16 h1 = __float2bfloat16(v.y);
    __nv_bfloat16 h2 = __float2bfloat16(v.z);
    __nv_bfloat16 h3 = __float2bfloat16(v.w);
    __nv_bfloat16 l0 = __float2bfloat16(v.x - __bfloat162float(h0));
    __nv_bfloat16 l1 = __float2bfloat16(v.y - __bfloat162float(h1));
    __nv_bfloat16 l2 = __float2bfloat16(v.z - __bfloat162float(h2));
    __nv_bfloat16 l3 = __float2bfloat16(v.w - __bfloat162float(h3));
    ushort4 H = {__bfloat16_as_ushort(h0), __bfloat16_as_ushort(h1),
                 __bfloat16_as_ushort(h2), __bfloat16_as_ushort(h3)};
    ushort4 L = {__bfloat16_as_ushort(l0), __bfloat16_as_ushort(l1),
                 __bfloat16_as_ushort(l2), __bfloat16_as_ushort(l3)};
    hi[i] = H;
    lo[i] = L;
}

// ------------- fp32 [K,N] -> transposed bf16 hi/lo [N,K] --------------------
__global__ __launch_bounds__(256) void splitT_kernel(
    const float* __restrict__ W,
    __nv_bfloat16* __restrict__ hiT, __nv_bfloat16* __restrict__ loT,
    int K, int N)
{
    __shared__ float tile[32][33];
    const int tx = threadIdx.x;         // 0..31
    const int ty = threadIdx.y;         // 0..7
    const int n0 = blockIdx.x * 32;
    const int k0 = blockIdx.y * 32;
    #pragma unroll
    for (int i = 0; i < 4; i++)
        tile[ty + 8*i][tx] = W[(size_t)(k0 + ty + 8*i) * N + n0 + tx];
    __syncthreads();
    #pragma unroll
    for (int i = 0; i < 4; i++) {
        float v = tile[tx][ty + 8*i];
        __nv_bfloat16 h = __float2bfloat16(v);
        __nv_bfloat16 l = __float2bfloat16(v - __bfloat162float(h));
        size_t o = (size_t)(n0 + ty + 8*i) * K + k0 + tx;
        hiT[o] = h;
        loT[o] = l;
    }
}

// ---------------- warp-MMA GEMM: C[M,N] = A @ B^T (3-term bf16 split) -------
// A{hi,lo}: [M,K] bf16 row-major. B{hi,lo}: [N,K] bf16 row-major.
// CTA tile 128x128, BK=32, 8 warps (each 32m x 64n), cp.async double buffer.
// smem tiles: [128 rows][32 bf16 + 8 pad] -> 80B row stride (conflict-free
// ldmatrix: 8 rows * 80B mod 128B hit distinct 16B banks).
#define BK 32
#define ROWB 80
#define TILE_B (128 * ROWB)          // 10240
#define STAGE_B (4 * TILE_B)         // 40960
#define GSMEM_BYTES (2 * STAGE_B)    // 81920

__global__ __launch_bounds__(256, 1) void gemm3_kernel(
    const __nv_bfloat16* __restrict__ Ahi, const __nv_bfloat16* __restrict__ Alo,
    const __nv_bfloat16* __restrict__ Bhi, const __nv_bfloat16* __restrict__ Blo,
    float* __restrict__ C, int M, int N, int K)
{
    extern __shared__ char sb[];
    const uint32_t sbase = smem_u32(sb);
    const int tid = threadIdx.x;
    const int wid = tid >> 5;
    const int lid = tid & 31;
    const int wm = wid & 3;              // 4 m-groups of 32 rows
    const int wn = wid >> 2;             // 2 n-groups of 64 cols

    const int row0 = blockIdx.y * 128;
    const int col0 = blockIdx.x * 128;

    const __nv_bfloat16* gp[4] = {
        Ahi + (size_t)row0 * K, Alo + (size_t)row0 * K,
        Bhi + (size_t)col0 * K, Blo + (size_t)col0 * K
    };

    float acc[2][8][4];
    #pragma unroll
    for (int mi = 0; mi < 2; mi++)
        #pragma unroll
        for (int g = 0; g < 8; g++)
            #pragma unroll
            for (int e = 0; e < 4; e++) acc[mi][g][e] = 0.f;

    // ldmatrix lane-address components
    const int a_row = lid & 15;
    const int a_kx  = (lid >> 4) << 3;
    const int b_row = (lid & 7) + ((lid >> 4) << 3);
    const int b_kx  = ((lid >> 3) & 1) << 3;

    const int nkc = K / BK;

    // prefetch stage 0
    {
        #pragma unroll
        for (int i = 0; i < 8; i++) {
            int chunk = tid + i * 256;
            int tile = chunk >> 9;
            int w = chunk & 511;
            int r = w >> 2, c = w & 3;
            const __nv_bfloat16* g = gp[tile] + (size_t)r * K + c * 8;
            uint32_t s = sbase + tile * TILE_B + r * ROWB + c * 16;
            CP_ASYNC16(s, g);
        }
        CP_COMMIT();
    }

    for (int kc = 0; kc < nkc; kc++) {
        if (kc + 1 < nkc) {
            int k0 = (kc + 1) * BK;
            uint32_t stg = sbase + ((kc + 1) & 1) * STAGE_B;
            #pragma unroll
            for (int i = 0; i < 8; i++) {
                int chunk = tid + i * 256;
                int tile = chunk >> 9;
                int w = chunk & 511;
                int r = w >> 2, c = w & 3;
                const __nv_bfloat16* g = gp[tile] + (size_t)r * K + k0 + c * 8;
                uint32_t s = stg + tile * TILE_B + r * ROWB + c * 16;
                CP_ASYNC16(s, g);
            }
            CP_COMMIT();
            CP_WAIT(1);
        } else {
            CP_WAIT(0);
        }
        __syncthreads();

        const uint32_t st = sbase + (kc & 1) * STAGE_B;
        #pragma unroll
        for (int ks = 0; ks < 2; ks++) {
            const int k0 = ks * 16;
            uint32_t ah[2][4], al[2][4];
            #pragma unroll
            for (int mi = 0; mi < 2; mi++) {
                uint32_t aoff = (uint32_t)((wm * 32 + mi * 16 + a_row) * ROWB
                                           + (k0 + a_kx) * 2);
                ldsm_x4(ah[mi], st + aoff);
                ldsm_x4(al[mi], st + TILE_B + aoff);
            }
            #pragma unroll
            for (int g4 = 0; g4 < 4; g4++) {
                uint32_t bh[4], bl[4];
                uint32_t boff = (uint32_t)((wn * 64 + g4 * 16 + b_row) * ROWB
                                           + (k0 + b_kx) * 2);
                ldsm_x4(bh, st + 2 * TILE_B + boff);
                ldsm_x4(bl, st + 3 * TILE_B + boff);
                #pragma unroll
                for (int mi = 0; mi < 2; mi++) {
                    #pragma unroll
                    for (int sub = 0; sub < 2; sub++) {
                        float* d = acc[mi][g4 * 2 + sub];
                        mma16816(d, ah[mi], bh + sub * 2);
                        mma16816(d, ah[mi], bl + sub * 2);
                        mma16816(d, al[mi], bh + sub * 2);
                    }
                }
            }
        }
        __syncthreads();
    }

    // store C
    const int cr = lid >> 2;
    const int cc = (lid & 3) * 2;
    #pragma unroll
    for (int mi = 0; mi < 2; mi++) {
        #pragma unroll
        for (int g = 0; g < 8; g++) {
            int rg = row0 + wm * 32 + mi * 16 + cr;
            int cg = col0 + wn * 64 + g * 8 + cc;
            float2 v0 = {acc[mi][g][0], acc[mi][g][1]};
            float2 v1 = {acc[mi][g][2], acc[mi][g][3]};
            *(float2*)(C + (size_t)rg * N + cg)       = v0;
            *(float2*)(C + (size_t)(rg + 8) * N + cg) = v1;
        }
    }
}

// ---------------- RoPE (in-place) ------------------------------------------
__global__ void rope_kernel(float* __restrict__ t,
                            const float* __restrict__ fcos,
                            const float* __restrict__ fsin,
                            int nheads, int total_pairs)
{
    int idx = blockIdx.x * blockDim.x + threadIdx.x;
    if (idx >= total_pairs) return;
    int d = idx & 63;
    int row = idx >> 6;
    int s = (row / nheads) % SEQ;
    size_t base = (size_t)row * HD;
    float c  = fcos[s * 64 + d];
    float sn = fsin[s * 64 + d];
    float t1 = t[base + d];
    float t2 = t[base + 64 + d];
    t[base + d]      = t1 * c  - t2 * sn;
    t[base + 64 + d] = t1 * sn + t2 * c;
}

// ---------------- Flash attention (causal, GQA) -----------------------------
#define BQ 64
#define BKT 64
#define PS_STRIDE 65

__global__ __launch_bounds__(256) void flash_attn_kernel(
    const float* __restrict__ Q, const float* __restrict__ K,
    const float* __restrict__ V, float* __restrict__ O)
{
    extern __shared__ float sm[];
    float* Qt  = sm;
    float* Kt  = Qt + HD * BQ;
    float* Vs  = Kt + HD * BKT;
    float* Ps  = Vs + BKT * HD;
    float* m_s = Ps + BQ * PS_STRIDE;
    float* l_s = m_s + BQ;
    float* e_s = l_s + BQ;

    const int qb = blockIdx.x;
    const int h  = blockIdx.y;
    const int b  = blockIdx.z;
    const int kvh = h / GROUPS;
    const int tid = threadIdx.x;
    const int tx = tid & 15;
    const int ty = tid >> 4;

    const float scale = 0.08838834764831845f;

    const float* Qg = Q + ((size_t)(b * SEQ + qb * BQ) * NH + h) * HD;
    for (int f = tid; f < BQ * HD / 4; f += 256) {
        int q = f >> 5;
        int d4 = (f & 31) << 2;
        float4 v = *(const float4*)(Qg + (size_t)q * NH * HD + d4);
        Qt[(d4 + 0) * BQ + q] = v.x;
        Qt[(d4 + 1) * BQ + q] = v.y;
        Qt[(d4 + 2) * BQ + q] = v.z;
        Qt[(d4 + 3) * BQ + q] = v.w;
    }
    if (tid < BQ) { m_s[tid] = -1e30f; l_s[tid] = 0.f; }

    float acc[4][8];
    #pragma unroll
    for (int i = 0; i < 4; i++)
        #pragma unroll
        for (int j = 0; j < 8; j++) acc[i][j] = 0.f;

    const int nkt = qb + 1;
    for (int kt = 0; kt < nkt; kt++) {
        __syncthreads();
        const float* Kg = K + ((size_t)(b * SEQ + kt * BKT) * NKV + kvh) * HD;
        const float* Vg = V + ((size_t)(b * SEQ + kt * BKT) * NKV + kvh) * HD;
        for (int f = tid; f < BKT * HD / 4; f += 256) {
            int k = f >> 5;
            int d4 = (f & 31) << 2;
            float4 kv = *(const float4*)(Kg + (size_t)k * NKV * HD + d4);
            Kt[(d4 + 0) * BKT + k] = kv.x;
            Kt[(d4 + 1) * BKT + k] = kv.y;
            Kt[(d4 + 2) * BKT + k] = kv.z;
            Kt[(d4 + 3) * BKT + k] = kv.w;
            float4 vv = *(const float4*)(Vg + (size_t)k * NKV * HD + d4);
            *(float4*)(Vs + (size_t)k * HD + d4) = vv;
        }
        __syncthreads();

        float s[4][4];
        #pragma unroll
        for (int i = 0; i < 4; i++)
            #pragma unroll
            for (int j = 0; j < 4; j++) s[i][j] = 0.f;

        #pragma unroll 4
        for (int d = 0; d < HD; d++) {
            float qv[4], kv[4];
            *(float4*)qv = *(const float4*)(Qt + d * BQ + ty * 4);
            *(float4*)kv = *(const float4*)(Kt + d * BKT + tx * 4);
            #pragma unroll
            for (int i = 0; i < 4; i++)
                #pragma unroll
                for (int j = 0; j < 4; j++)
                    s[i][j] += qv[i] * kv[j];
        }

        const int k0 = kt * BKT;
        const bool diag = (kt == qb);
        #pragma unroll
        for (int i = 0; i < 4; i++) {
            int qg = qb * BQ + ty * 4 + i;
            #pragma unroll
            for (int j = 0; j < 4; j++) {
                float v = s[i][j] * scale;
                if (diag && (k0 + tx * 4 + j > qg)) v = -1e30f;
                Ps[(ty * 4 + i) * PS_STRIDE + tx * 4 + j] = v;
            }
        }
        __syncthreads();

        if (tid < BQ) {
            float* row = Ps + tid * PS_STRIDE;
            float rmax = row[0];
            #pragma unroll 8
            for (int c = 1; c < BKT; c++) rmax = fmaxf(rmax, row[c]);
            float mnew = fmaxf(m_s[tid], rmax);
            float esc  = __expf(m_s[tid] - mnew);
            float sum = 0.f;
            #pragma unroll 8
            for (int c = 0; c < BKT; c++) {
                float p = __expf(row[c] - mnew);
                row[c] = p;
                sum += p;
            }
            l_s[tid] = l_s[tid] * esc + sum;
            m_s[tid] = mnew;
            e_s[tid] = esc;
        }
        __syncthreads();

        float esc_i[4];
        #pragma unroll
        for (int i = 0; i < 4; i++) esc_i[i] = e_s[ty * 4 + i];
        #pragma unroll
        for (int i = 0; i < 4; i++)
            #pragma unroll
            for (int j = 0; j < 8; j++) acc[i][j] *= esc_i[i];

        #pragma unroll 4
        for (int kk = 0; kk < BKT; kk++) {
            float p[4];
            #pragma unroll
            for (int i = 0; i < 4; i++) p[i] = Ps[(ty * 4 + i) * PS_STRIDE + kk];
            float vv[8];
            *(float4*)&vv[0] = *(const float4*)(Vs + (size_t)kk * HD + tx * 8);
            *(float4*)&vv[4] = *(const float4*)(Vs + (size_t)kk * HD + tx * 8 + 4);
            #pragma unroll
            for (int i = 0; i < 4; i++)
                #pragma unroll
                for (int j = 0; j < 8; j++)
                    acc[i][j] += p[i] * vv[j];
        }
    }

    float* Og = O + ((size_t)(b * SEQ + qb * BQ) * NH + h) * HD;
    #pragma unroll
    for (int i = 0; i < 4; i++) {
        float linv = 1.f / l_s[ty * 4 + i];
        float4 v0 = {acc[i][0] * linv, acc[i][1] * linv,
                     acc[i][2] * linv, acc[i][3] * linv};
        float4 v1 = {acc[i][4] * linv, acc[i][5] * linv,
                     acc[i][6] * linv, acc[i][7] * linv};
        size_t orow = (size_t)(ty * 4 + i) * NH * HD + tx * 8;
        *(float4*)(Og + orow)     = v0;
        *(float4*)(Og + orow + 4) = v1;
    }
}

// ---------------- launch ----------------------------------------------------
template <typename T>
static T* sym_addr(const void* sym)
{
    void* p = nullptr;
    cudaGetSymbolAddress(&p, sym);
    return (T*)p;
}

extern "C" void kernel_launch(void* const* d_in, const int* in_sizes, int n_in,
                              void* d_out, int out_size)
{
    const float* x    = (const float*)d_in[0];
    const float* wq   = (const float*)d_in[1];
    const float* wk   = (const float*)d_in[2];
    const float* wv   = (const float*)d_in[3];
    const float* wo   = (const float*)d_in[4];
    const float* fcos = (const float*)d_in[5];
    const float* fsin = (const float*)d_in[6];
    float* out = (float*)d_out;

    float* q    = sym_addr<float>(g_q);
    float* k    = sym_addr<float>(g_k);
    float* v    = sym_addr<float>(g_v);
    float* attn = sym_addr<float>(g_attn);
    __nv_bfloat16* xhi  = sym_addr<__nv_bfloat16>(g_xhi);
    __nv_bfloat16* xlo  = sym_addr<__nv_bfloat16>(g_xlo);
    __nv_bfloat16* ahi  = sym_addr<__nv_bfloat16>(g_ahi);
    __nv_bfloat16* alo  = sym_addr<__nv_bfloat16>(g_alo);
    __nv_bfloat16* wqh  = sym_addr<__nv_bfloat16>(g_wqhiT);
    __nv_bfloat16* wql  = sym_addr<__nv_bfloat16>(g_wqloT);
    __nv_bfloat16* wkh  = sym_addr<__nv_bfloat16>(g_wkhiT);
    __nv_bfloat16* wkl  = sym_addr<__nv_bfloat16>(g_wkloT);
    __nv_bfloat16* wvh  = sym_addr<__nv_bfloat16>(g_wvhiT);
    __nv_bfloat16* wvl  = sym_addr<__nv_bfloat16>(g_wvloT);
    __nv_bfloat16* woh  = sym_addr<__nv_bfloat16>(g_wohiT);
    __nv_bfloat16* wol  = sym_addr<__nv_bfloat16>(g_woloT);

    static bool attrs_set = false;
    if (!attrs_set) {
        cudaFuncSetAttribute(gemm3_kernel,
                             cudaFuncAttributeMaxDynamicSharedMemorySize, GSMEM_BYTES);
        size_t fsm = (size_t)(HD * BQ + HD * BKT + BKT * HD
                              + BQ * PS_STRIDE + 3 * BQ) * sizeof(float);
        cudaFuncSetAttribute(flash_attn_kernel,
                             cudaFuncAttributeMaxDynamicSharedMemorySize, (int)fsm);
        attrs_set = true;
    }

    // Split/transpose conversions
    {
        int n4 = MROWS * HID / 4;
        split_kernel<<<(n4 + 255) / 256, 256>>>((const float4*)x,
                                                (ushort4*)xhi, (ushort4*)xlo, n4);
        splitT_kernel<<<dim3(HID/32, HID/32), dim3(32,8)>>>(wq, wqh, wql, HID, HID);
        splitT_kernel<<<dim3((NKV*HD)/32, HID/32), dim3(32,8)>>>(wk, wkh, wkl, HID, NKV*HD);
        splitT_kernel<<<dim3((NKV*HD)/32, HID/32), dim3(32,8)>>>(wv, wvh, wvl, HID, NKV*HD);
        splitT_kernel<<<dim3(HID/32, HID/32), dim3(32,8)>>>(wo, woh, wol, HID, HID);
    }

    // QKV projections (tensor cores, 3-term bf16)
    gemm3_kernel<<<dim3((NH*HD)/128, MROWS/128), 256, GSMEM_BYTES>>>(
        xhi, xlo, wqh, wql, q, MROWS, NH*HD, HID);
    gemm3_kernel<<<dim3((NKV*HD)/128, MROWS/128), 256, GSMEM_BYTES>>>(
        xhi, xlo, wkh, wkl, k, MROWS, NKV*HD, HID);
    gemm3_kernel<<<dim3((NKV*HD)/128, MROWS/128), 256, GSMEM_BYTES>>>(
        xhi, xlo, wvh, wvl, v, MROWS, NKV*HD, HID);

    // RoPE
    {
        int pq = MROWS * NH * 64;
        int pk = MROWS * NKV * 64;
        rope_kernel<<<(pq + 255) / 256, 256>>>(q, fcos, fsin, NH, pq);
        rope_kernel<<<(pk + 255) / 256, 256>>>(k, fcos, fsin, NKV, pk);
    }

    // Flash attention (fp32)
    {
        size_t fsm = (size_t)(HD * BQ + HD * BKT + BKT * HD
                              + BQ * PS_STRIDE + 3 * BQ) * sizeof(float);
        flash_attn_kernel<<<dim3(SEQ / BQ, NH, BATCH), 256, fsm>>>(q, k, v, attn);
    }

    // Output projection
    {
        int n4 = MROWS * HID / 4;
        split_kernel<<<(n4 + 255) / 256, 256>>>((const float4*)attn,
                                                (ushort4*)ahi, (ushort4*)alo, n4);
        gemm3_kernel<<<dim3(HID/128, MROWS/128), 256, GSMEM_BYTES>>>(
            ahi, alo, woh, wol, out, MROWS, HID, HID);
    }
}

// round 4
// speedup vs baseline: 2.5550x; 1.3799x over previous
#include <cuda_runtime.h>
#include <cuda_bf16.h>
#include <math.h>
#include <stdint.h>

// Problem constants
#define BATCH 2
#define SEQ   1024
#define HID   4096
#define NH    32
#define NKV   8
#define HD    128
#define MROWS (BATCH*SEQ)          // 2048
#define GROUPS (NH/NKV)            // 4

// ======================= warp MMA helpers (sm_80+ path) =====================
__device__ __forceinline__ uint32_t smem_u32(const void* p) {
    uint32_t a;
    asm("{ .reg .u64 t; cvta.to.shared.u64 t, %1; cvt.u32.u64 %0, t; }"
        : "=r"(a) : "l"(p));
    return a;
}

__device__ __forceinline__ void ldsm_x4(uint32_t* r, uint32_t addr) {
    asm volatile("ldmatrix.sync.aligned.m8n8.x4.shared.b16 {%0,%1,%2,%3}, [%4];"
                 : "=r"(r[0]), "=r"(r[1]), "=r"(r[2]), "=r"(r[3]) : "r"(addr));
}
__device__ __forceinline__ void ldsm_x4_t(uint32_t* r, uint32_t addr) {
    asm volatile("ldmatrix.sync.aligned.m8n8.x4.trans.shared.b16 {%0,%1,%2,%3}, [%4];"
                 : "=r"(r[0]), "=r"(r[1]), "=r"(r[2]), "=r"(r[3]) : "r"(addr));
}

__device__ __forceinline__ void mma16816(float* d, const uint32_t* a,
                                         const uint32_t* b) {
    asm volatile("mma.sync.aligned.m16n8k16.row.col.f32.bf16.bf16.f32 "
                 "{%0,%1,%2,%3}, {%4,%5,%6,%7}, {%8,%9}, {%0,%1,%2,%3};"
                 : "+f"(d[0]), "+f"(d[1]), "+f"(d[2]), "+f"(d[3])
                 : "r"(a[0]), "r"(a[1]), "r"(a[2]), "r"(a[3]),
                   "r"(b[0]), "r"(b[1]));
}

#define CP_ASYNC16(smem, gptr) \
    asm volatile("cp.async.cg.shared.global [%0], [%1], 16;" \
                 :: "r"(smem), "l"(gptr))
#define CP_COMMIT() asm volatile("cp.async.commit_group;" ::: "memory")
#define CP_WAIT(N)  asm volatile("cp.async.wait_group %0;" :: "n"(N) : "memory")

// ---------------- scratch (device globals; no cudaMalloc allowed) ----------
__device__ float g_q[(size_t)MROWS * NH * HD];
__device__ float g_k[(size_t)MROWS * NKV * HD];
__device__ float g_v[(size_t)MROWS * NKV * HD];
__device__ float g_attn[(size_t)MROWS * NH * HD];

__device__ __nv_bfloat16 g_xhi[(size_t)MROWS * HID];
__device__ __nv_bfloat16 g_xlo[(size_t)MROWS * HID];
__device__ __nv_bfloat16 g_ahi[(size_t)MROWS * HID];
__device__ __nv_bfloat16 g_alo[(size_t)MROWS * HID];
__device__ __nv_bfloat16 g_wqhiT[(size_t)HID * HID];
__device__ __nv_bfloat16 g_wqloT[(size_t)HID * HID];
__device__ __nv_bfloat16 g_wkhiT[(size_t)(NKV*HD) * HID];
__device__ __nv_bfloat16 g_wkloT[(size_t)(NKV*HD) * HID];
__device__ __nv_bfloat16 g_wvhiT[(size_t)(NKV*HD) * HID];
__device__ __nv_bfloat16 g_wvloT[(size_t)(NKV*HD) * HID];
__device__ __nv_bfloat16 g_wohiT[(size_t)HID * HID];
__device__ __nv_bfloat16 g_woloT[(size_t)HID * HID];

// bf16 attention operands (post-RoPE)
__device__ __nv_bfloat16 g_qh[(size_t)MROWS * NH * HD];
__device__ __nv_bfloat16 g_ql[(size_t)MROWS * NH * HD];
__device__ __nv_bfloat16 g_kh[(size_t)MROWS * NKV * HD];
__device__ __nv_bfloat16 g_kl[(size_t)MROWS * NKV * HD];
__device__ __nv_bfloat16 g_vh[(size_t)MROWS * NKV * HD];
__device__ __nv_bfloat16 g_vl[(size_t)MROWS * NKV * HD];

// ---------------- fp32 -> bf16 hi/lo split (elementwise) --------------------
__global__ void split_kernel(const float4* __restrict__ in,
                             ushort4* __restrict__ hi,
                             ushort4* __restrict__ lo, int n4)
{
    int i = blockIdx.x * blockDim.x + threadIdx.x;
    if (i >= n4) return;
    float4 v = in[i];
    __nv_bfloat16 h0 = __float2bfloat16(v.x);
    __nv_bfloat16 h1 = __float2bfloat16(v.y);
    __nv_bfloat16 h2 = __float2bfloat16(v.z);
    __nv_bfloat16 h3 = __float2bfloat16(v.w);
    __nv_bfloat16 l0 = __float2bfloat16(v.x - __bfloat162float(h0));
    __nv_bfloat16 l1 = __float2bfloat16(v.y - __bfloat162float(h1));
    __nv_bfloat16 l2 = __float2bfloat16(v.z - __bfloat162float(h2));
    __nv_bfloat16 l3 = __float2bfloat16(v.w - __bfloat162float(h3));
    ushort4 H = {__bfloat16_as_ushort(h0), __bfloat16_as_ushort(h1),
                 __bfloat16_as_ushort(h2), __bfloat16_as_ushort(h3)};
    ushort4 L = {__bfloat16_as_ushort(l0), __bfloat16_as_ushort(l1),
                 __bfloat16_as_ushort(l2), __bfloat16_as_ushort(l3)};
    hi[i] = H;
    lo[i] = L;
}

// ------------- fp32 [K,N] -> transposed bf16 hi/lo [N,K] --------------------
__global__ __launch_bounds__(256) void splitT_kernel(
    const float* __restrict__ W,
    __nv_bfloat16* __restrict__ hiT, __nv_bfloat16* __restrict__ loT,
    int K, int N)
{
    __shared__ float tile[32][33];
    const int tx = threadIdx.x;
    const int ty = threadIdx.y;
    const int n0 = blockIdx.x * 32;
    const int k0 = blockIdx.y * 32;
    #pragma unroll
    for (int i = 0; i < 4; i++)
        tile[ty + 8*i][tx] = W[(size_t)(k0 + ty + 8*i) * N + n0 + tx];
    __syncthreads();
    #pragma unroll
    for (int i = 0; i < 4; i++) {
        float v = tile[tx][ty + 8*i];
        __nv_bfloat16 h = __float2bfloat16(v);
        __nv_bfloat16 l = __float2bfloat16(v - __bfloat162float(h));
        size_t o = (size_t)(n0 + ty + 8*i) * K + k0 + tx;
        hiT[o] = h;
        loT[o] = l;
    }
}

// ------------- fused RoPE + prescale + bf16 hi/lo split ---------------------
__global__ void rope_split_kernel(const float* __restrict__ src,
                                  __nv_bfloat16* __restrict__ hi,
                                  __nv_bfloat16* __restrict__ lo,
                                  const float* __restrict__ fcos,
                                  const float* __restrict__ fsin,
                                  int nheads, float prescale, int total_pairs)
{
    int idx = blockIdx.x * blockDim.x + threadIdx.x;
    if (idx >= total_pairs) return;
    int d = idx & 63;
    int row = idx >> 6;
    int s = (row / nheads) % SEQ;
    size_t base = (size_t)row * HD;
    float c  = fcos[s * 64 + d];
    float sn = fsin[s * 64 + d];
    float t1 = src[base + d];
    float t2 = src[base + 64 + d];
    float r1 = (t1 * c  - t2 * sn) * prescale;
    float r2 = (t1 * sn + t2 * c)  * prescale;
    __nv_bfloat16 h1 = __float2bfloat16(r1);
    __nv_bfloat16 h2 = __float2bfloat16(r2);
    hi[base + d]      = h1;
    hi[base + 64 + d] = h2;
    lo[base + d]      = __float2bfloat16(r1 - __bfloat162float(h1));
    lo[base + 64 + d] = __float2bfloat16(r2 - __bfloat162float(h2));
}

// ---------------- warp-MMA GEMM: C[M,N] = A @ B^T (3-term bf16 split) -------
#define BK 32
#define ROWB 80
#define TILE_B (128 * ROWB)
#define STAGE_B (4 * TILE_B)
#define GSMEM_BYTES (2 * STAGE_B)

__global__ __launch_bounds__(256, 1) void gemm3_kernel(
    const __nv_bfloat16* __restrict__ Ahi, const __nv_bfloat16* __restrict__ Alo,
    const __nv_bfloat16* __restrict__ Bhi, const __nv_bfloat16* __restrict__ Blo,
    float* __restrict__ C, int M, int N, int K)
{
    extern __shared__ char sb[];
    const uint32_t sbase = smem_u32(sb);
    const int tid = threadIdx.x;
    const int wid = tid >> 5;
    const int lid = tid & 31;
    const int wm = wid & 3;
    const int wn = wid >> 2;

    const int row0 = blockIdx.y * 128;
    const int col0 = blockIdx.x * 128;

    const __nv_bfloat16* gp[4] = {
        Ahi + (size_t)row0 * K, Alo + (size_t)row0 * K,
        Bhi + (size_t)col0 * K, Blo + (size_t)col0 * K
    };

    float acc[2][8][4];
    #pragma unroll
    for (int mi = 0; mi < 2; mi++)
        #pragma unroll
        for (int g = 0; g < 8; g++)
            #pragma unroll
            for (int e = 0; e < 4; e++) acc[mi][g][e] = 0.f;

    const int a_row = lid & 15;
    const int a_kx  = (lid >> 4) << 3;
    const int b_row = (lid & 7) + ((lid >> 4) << 3);
    const int b_kx  = ((lid >> 3) & 1) << 3;

    const int nkc = K / BK;

    {
        #pragma unroll
        for (int i = 0; i < 8; i++) {
            int chunk = tid + i * 256;
            int tile = chunk >> 9;
            int w = chunk & 511;
            int r = w >> 2, c = w & 3;
            const __nv_bfloat16* g = gp[tile] + (size_t)r * K + c * 8;
            uint32_t s = sbase + tile * TILE_B + r * ROWB + c * 16;
            CP_ASYNC16(s, g);
        }
        CP_COMMIT();
    }

    for (int kc = 0; kc < nkc; kc++) {
        if (kc + 1 < nkc) {
            int k0 = (kc + 1) * BK;
            uint32_t stg = sbase + ((kc + 1) & 1) * STAGE_B;
            #pragma unroll
            for (int i = 0; i < 8; i++) {
                int chunk = tid + i * 256;
                int tile = chunk >> 9;
                int w = chunk & 511;
                int r = w >> 2, c = w & 3;
                const __nv_bfloat16* g = gp[tile] + (size_t)r * K + k0 + c * 8;
                uint32_t s = stg + tile * TILE_B + r * ROWB + c * 16;
                CP_ASYNC16(s, g);
            }
            CP_COMMIT();
            CP_WAIT(1);
        } else {
            CP_WAIT(0);
        }
        __syncthreads();

        const uint32_t st = sbase + (kc & 1) * STAGE_B;
        #pragma unroll
        for (int ks = 0; ks < 2; ks++) {
            const int k0 = ks * 16;
            uint32_t ah[2][4], al[2][4];
            #pragma unroll
            for (int mi = 0; mi < 2; mi++) {
                uint32_t aoff = (uint32_t)((wm * 32 + mi * 16 + a_row) * ROWB
                                           + (k0 + a_kx) * 2);
                ldsm_x4(ah[mi], st + aoff);
                ldsm_x4(al[mi], st + TILE_B + aoff);
            }
            #pragma unroll
            for (int g4 = 0; g4 < 4; g4++) {
                uint32_t bh[4], bl[4];
                uint32_t boff = (uint32_t)((wn * 64 + g4 * 16 + b_row) * ROWB
                                           + (k0 + b_kx) * 2);
                ldsm_x4(bh, st + 2 * TILE_B + boff);
                ldsm_x4(bl, st + 3 * TILE_B + boff);
                #pragma unroll
                for (int mi = 0; mi < 2; mi++) {
                    #pragma unroll
                    for (int sub = 0; sub < 2; sub++) {
                        float* d = acc[mi][g4 * 2 + sub];
                        mma16816(d, ah[mi], bh + sub * 2);
                        mma16816(d, ah[mi], bl + sub * 2);
                        mma16816(d, al[mi], bh + sub * 2);
                    }
                }
            }
        }
        __syncthreads();
    }

    const int cr = lid >> 2;
    const int cc = (lid & 3) * 2;
    #pragma unroll
    for (int mi = 0; mi < 2; mi++) {
        #pragma unroll
        for (int g = 0; g < 8; g++) {
            int rg = row0 + wm * 32 + mi * 16 + cr;
            int cg = col0 + wn * 64 + g * 8 + cc;
            float2 v0 = {acc[mi][g][0], acc[mi][g][1]};
            float2 v1 = {acc[mi][g][2], acc[mi][g][3]};
            *(float2*)(C + (size_t)rg * N + cg)       = v0;
            *(float2*)(C + (size_t)(rg + 8) * N + cg) = v1;
        }
    }
}

// ---------------- Flash attention, HMMA (causal, GQA) -----------------------
// CTA: 128 q-rows x whole-head pass over 64-key tiles. 8 warps, 16 q-rows each.
// Q/K 3-term bf16 (hi/lo), P single bf16, V 2-term (hi/lo).
// smem rows padded to 272B -> conflict-free ldmatrix.
#define FROWB 272
#define FQ_TILE (128 * FROWB)          // 34816 per tensor
#define FKV_TILE (64 * FROWB)          // 17408 per tensor
#define FSTAGE (4 * FKV_TILE)          // 69632: khi,klo,vhi,vlo
#define FSMEM (2 * FQ_TILE + 2 * FSTAGE) // 208896

__global__ __launch_bounds__(256, 1) void flash_mma_kernel(
    const __nv_bfloat16* __restrict__ Qh, const __nv_bfloat16* __restrict__ Ql,
    const __nv_bfloat16* __restrict__ Kh, const __nv_bfloat16* __restrict__ Kl,
    const __nv_bfloat16* __restrict__ Vh, const __nv_bfloat16* __restrict__ Vl,
    float* __restrict__ O)
{
    extern __shared__ char sb[];
    const uint32_t smq = smem_u32(sb);                // qhi, qlo
    const uint32_t smkv = smq + 2 * FQ_TILE;          // 2 stages of khi,klo,vhi,vlo

    const int qb  = blockIdx.x;
    const int h   = blockIdx.y;
    const int b   = blockIdx.z;
    const int kvh = h / GROUPS;
    const int tid = threadIdx.x;
    const int wid = tid >> 5;
    const int lid = tid & 31;

    // ---- load Q tile (128 rows x 128 hd, hi+lo) ----
    {
        const __nv_bfloat16* qsrc[2] = {
            Qh + ((size_t)(b * SEQ + qb * 128) * NH + h) * HD,
            Ql + ((size_t)(b * SEQ + qb * 128) * NH + h) * HD
        };
        #pragma unroll
        for (int i = 0; i < 16; i++) {
            int chunk = tid + i * 256;           // 0..4095
            int t = chunk >> 11;                 // hi/lo
            int w = chunk & 2047;
            int r = w >> 4, x = w & 15;
            const __nv_bfloat16* g = qsrc[t] + (size_t)r * NH * HD + x * 8;
            CP_ASYNC16(smq + t * FQ_TILE + r * FROWB + x * 16, g);
        }
        CP_COMMIT();
    }

    const __nv_bfloat16* kvsrc[4] = {
        Kh + ((size_t)(b * SEQ) * NKV + kvh) * HD,
        Kl + ((size_t)(b * SEQ) * NKV + kvh) * HD,
        Vh + ((size_t)(b * SEQ) * NKV + kvh) * HD,
        Vl + ((size_t)(b * SEQ) * NKV + kvh) * HD
    };

    const int nkt = 2 * qb + 2;

    // prefetch stage 0
    {
        #pragma unroll
        for (int i = 0; i < 16; i++) {
            int chunk = tid + i * 256;           // 0..4095
            int t = chunk >> 10;                 // tensor 0..3
            int w = chunk & 1023;
            int r = w >> 4, x = w & 15;
            const __nv_bfloat16* g = kvsrc[t] + (size_t)r * NKV * HD + x * 8;
            CP_ASYNC16(smkv + t * FKV_TILE + r * FROWB + x * 16, g);
        }
        CP_COMMIT();
    }

    // per-warp state
    const int Q0 = wid * 16;                     // warp's q rows within CTA
    const int r0 = lid >> 2;                     // local row (and +8)
    const int c0 = (lid & 3) * 2;
    float m0 = -1e30f, m1 = -1e30f, l0 = 0.f, l1 = 0.f;
    float acc_o[16][4];
    #pragma unroll
    for (int t = 0; t < 16; t++)
        #pragma unroll
        for (int e = 0; e < 4; e++) acc_o[t][e] = 0.f;

    const int a_row = lid & 15;
    const int a_kx  = (lid >> 4) << 3;
    const int b_row = (lid & 7) + ((lid >> 4) << 3);
    const int b_kx  = ((lid >> 3) & 1) << 3;

    for (int kt = 0; kt < nkt; kt++) {
        __syncthreads();   // everyone done with the buffer we're about to fill
        if (kt + 1 < nkt) {
            int k0r = (kt + 1) * 64;
            uint32_t stg = smkv + ((kt + 1) & 1) * FSTAGE;
            #pragma unroll
            for (int i = 0; i < 16; i++) {
                int chunk = tid + i * 256;
                int t = chunk >> 10;
                int w = chunk & 1023;
                int r = w >> 4, x = w & 15;
                const __nv_bfloat16* g = kvsrc[t]
                    + (size_t)(k0r + r) * NKV * HD + x * 8;
                CP_ASYNC16(stg + t * FKV_TILE + r * FROWB + x * 16, g);
            }
            CP_COMMIT();
            CP_WAIT(1);
        } else {
            CP_WAIT(0);
        }
        __syncthreads();

        const uint32_t skh = smkv + (kt & 1) * FSTAGE;
        const uint32_t skl = skh + FKV_TILE;
        const uint32_t svh = skh + 2 * FKV_TILE;
        const uint32_t svl = skh + 3 * FKV_TILE;

        // ---- S = Q K^T (3-term) : per-warp 16 x 64 ----
        float s_acc[8][4];
        #pragma unroll
        for (int t = 0; t < 8; t++)
            #pragma unroll
            for (int e = 0; e < 4; e++) s_acc[t][e] = 0.f;

        #pragma unroll
        for (int kt8 = 0; kt8 < 8; kt8++) {
            uint32_t ah[4], al[4];
            uint32_t aoff = (uint32_t)((Q0 + a_row) * FROWB + (kt8 * 16 + a_kx) * 2);
            ldsm_x4(ah, smq + aoff);
            ldsm_x4(al, smq + FQ_TILE + aoff);
            #pragma unroll
            for (int ng = 0; ng < 4; ng++) {
                uint32_t bh[4], bl[4];
                uint32_t boff = (uint32_t)((ng * 16 + b_row) * FROWB
                                           + (kt8 * 16 + b_kx) * 2);
                ldsm_x4(bh, skh + boff);
                ldsm_x4(bl, skl + boff);
                #pragma unroll
                for (int sub = 0; sub < 2; sub++) {
                    float* d = s_acc[ng * 2 + sub];
                    mma16816(d, ah, bh + sub * 2);
                    mma16816(d, ah, bl + sub * 2);
                    mma16816(d, al, bh + sub * 2);
                }
            }
        }

        // ---- causal mask (only near the diagonal) ----
        const int k0 = kt * 64;
        const int qg0 = qb * 128 + Q0 + r0;      // rows qg0, qg0+8
        if (k0 + 63 > qb * 128 + Q0) {
            #pragma unroll
            for (int t = 0; t < 8; t++) {
                int kc = k0 + t * 8 + c0;
                if (kc     > qg0)     s_acc[t][0] = -1e30f;
                if (kc + 1 > qg0)     s_acc[t][1] = -1e30f;
                if (kc     > qg0 + 8) s_acc[t][2] = -1e30f;
                if (kc + 1 > qg0 + 8) s_acc[t][3] = -1e30f;
            }
        }

        // ---- online softmax (scores pre-scaled by 1/sqrt(d)*log2e) ----
        float mx0 = -1e30f, mx1 = -1e30f;
        #pragma unroll
        for (int t = 0; t < 8; t++) {
            mx0 = fmaxf(mx0, fmaxf(s_acc[t][0], s_acc[t][1]));
            mx1 = fmaxf(mx1, fmaxf(s_acc[t][2], s_acc[t][3]));
        }
        mx0 = fmaxf(mx0, __shfl_xor_sync(0xffffffffu, mx0, 1));
        mx0 = fmaxf(mx0, __shfl_xor_sync(0xffffffffu, mx0, 2));
        mx1 = fmaxf(mx1, __shfl_xor_sync(0xffffffffu, mx1, 1));
        mx1 = fmaxf(mx1, __shfl_xor_sync(0xffffffffu, mx1, 2));
        float mn0 = fmaxf(m0, mx0);
        float mn1 = fmaxf(m1, mx1);
        float e0 = exp2f(m0 - mn0);
        float e1 = exp2f(m1 - mn1);
        float rs0 = 0.f, rs1 = 0.f;
        #pragma unroll
        for (int t = 0; t < 8; t++) {
            s_acc[t][0] = exp2f(s_acc[t][0] - mn0);
            s_acc[t][1] = exp2f(s_acc[t][1] - mn0);
            s_acc[t][2] = exp2f(s_acc[t][2] - mn1);
            s_acc[t][3] = exp2f(s_acc[t][3] - mn1);
            rs0 += s_acc[t][0] + s_acc[t][1];
            rs1 += s_acc[t][2] + s_acc[t][3];
        }
        rs0 += __shfl_xor_sync(0xffffffffu, rs0, 1);
        rs0 += __shfl_xor_sync(0xffffffffu, rs0, 2);
        rs1 += __shfl_xor_sync(0xffffffffu, rs1, 1);
        rs1 += __shfl_xor_sync(0xffffffffu, rs1, 2);
        l0 = l0 * e0 + rs0;
        l1 = l1 * e1 + rs1;
        m0 = mn0;
        m1 = mn1;
        #pragma unroll
        for (int t = 0; t < 16; t++) {
            acc_o[t][0] *= e0;
            acc_o[t][1] *= e0;
            acc_o[t][2] *= e1;
            acc_o[t][3] *= e1;
        }

        // ---- O += P V (2-term) ----
        #pragma unroll
        for (int ktv = 0; ktv < 4; ktv++) {
            uint32_t a[4];
            __nv_bfloat162 p0 = __floats2bfloat162_rn(s_acc[2*ktv][0],   s_acc[2*ktv][1]);
            __nv_bfloat162 p1 = __floats2bfloat162_rn(s_acc[2*ktv][2],   s_acc[2*ktv][3]);
            __nv_bfloat162 p2 = __floats2bfloat162_rn(s_acc[2*ktv+1][0], s_acc[2*ktv+1][1]);
            __nv_bfloat162 p3 = __floats2bfloat162_rn(s_acc[2*ktv+1][2], s_acc[2*ktv+1][3]);
            a[0] = *(uint32_t*)&p0;
            a[1] = *(uint32_t*)&p1;
            a[2] = *(uint32_t*)&p2;
            a[3] = *(uint32_t*)&p3;
            #pragma unroll
            for (int ng = 0; ng < 8; ng++) {
                uint32_t voff = (uint32_t)((ktv * 16 + (lid & 15)) * FROWB
                                           + (ng * 16 + ((lid >> 4) << 3)) * 2);
                uint32_t bh[4], bl[4];
                ldsm_x4_t(bh, svh + voff);
                ldsm_x4_t(bl, svl + voff);
                mma16816(acc_o[ng * 2],     a, bh);
                mma16816(acc_o[ng * 2 + 1], a, bh + 2);
                mma16816(acc_o[ng * 2],     a, bl);
                mma16816(acc_o[ng * 2 + 1], a, bl + 2);
            }
        }
    }

    // ---- normalize + write out ----
    const float li0 = 1.f / l0;
    const float li1 = 1.f / l1;
    float* Og = O + ((size_t)(b * SEQ + qb * 128 + Q0) * NH + h) * HD;
    #pragma unroll
    for (int t = 0; t < 16; t++) {
        float2 v0 = {acc_o[t][0] * li0, acc_o[t][1] * li0};
        float2 v1 = {acc_o[t][2] * li1, acc_o[t][3] * li1};
        *(float2*)(Og + (size_t)r0 * NH * HD + t * 8 + c0)       = v0;
        *(float2*)(Og + (size_t)(r0 + 8) * NH * HD + t * 8 + c0) = v1;
    }
}

// ---------------- launch ----------------------------------------------------
template <typename T>
static T* sym_addr(const void* sym)
{
    void* p = nullptr;
    cudaGetSymbolAddress(&p, sym);
    return (T*)p;
}

extern "C" void kernel_launch(void* const* d_in, const int* in_sizes, int n_in,
                              void* d_out, int out_size)
{
    const float* x    = (const float*)d_in[0];
    const float* wq   = (const float*)d_in[1];
    const float* wk   = (const float*)d_in[2];
    const float* wv   = (const float*)d_in[3];
    const float* wo   = (const float*)d_in[4];
    const float* fcos = (const float*)d_in[5];
    const float* fsin = (const float*)d_in[6];
    float* out = (float*)d_out;

    float* q    = sym_addr<float>(g_q);
    float* k    = sym_addr<float>(g_k);
    float* v    = sym_addr<float>(g_v);
    float* attn = sym_addr<float>(g_attn);
    __nv_bfloat16* xhi  = sym_addr<__nv_bfloat16>(g_xhi);
    __nv_bfloat16* xlo  = sym_addr<__nv_bfloat16>(g_xlo);
    __nv_bfloat16* ahi  = sym_addr<__nv_bfloat16>(g_ahi);
    __nv_bfloat16* alo  = sym_addr<__nv_bfloat16>(g_alo);
    __nv_bfloat16* wqh  = sym_addr<__nv_bfloat16>(g_wqhiT);
    __nv_bfloat16* wql  = sym_addr<__nv_bfloat16>(g_wqloT);
    __nv_bfloat16* wkh  = sym_addr<__nv_bfloat16>(g_wkhiT);
    __nv_bfloat16* wkl  = sym_addr<__nv_bfloat16>(g_wkloT);
    __nv_bfloat16* wvh  = sym_addr<__nv_bfloat16>(g_wvhiT);
    __nv_bfloat16* wvl  = sym_addr<__nv_bfloat16>(g_wvloT);
    __nv_bfloat16* woh  = sym_addr<__nv_bfloat16>(g_wohiT);
    __nv_bfloat16* wol  = sym_addr<__nv_bfloat16>(g_woloT);
    __nv_bfloat16* qh = sym_addr<__nv_bfloat16>(g_qh);
    __nv_bfloat16* ql = sym_addr<__nv_bfloat16>(g_ql);
    __nv_bfloat16* kh = sym_addr<__nv_bfloat16>(g_kh);
    __nv_bfloat16* kl = sym_addr<__nv_bfloat16>(g_kl);
    __nv_bfloat16* vh = sym_addr<__nv_bfloat16>(g_vh);
    __nv_bfloat16* vl = sym_addr<__nv_bfloat16>(g_vl);

    static bool attrs_set = false;
    if (!attrs_set) {
        cudaFuncSetAttribute(gemm3_kernel,
                             cudaFuncAttributeMaxDynamicSharedMemorySize, GSMEM_BYTES);
        cudaFuncSetAttribute(flash_mma_kernel,
                             cudaFuncAttributeMaxDynamicSharedMemorySize, FSMEM);
        attrs_set = true;
    }

    // Split/transpose conversions
    {
        int n4 = MROWS * HID / 4;
        split_kernel<<<(n4 + 255) / 256, 256>>>((const float4*)x,
                                                (ushort4*)xhi, (ushort4*)xlo, n4);
        splitT_kernel<<<dim3(HID/32, HID/32), dim3(32,8)>>>(wq, wqh, wql, HID, HID);
        splitT_kernel<<<dim3((NKV*HD)/32, HID/32), dim3(32,8)>>>(wk, wkh, wkl, HID, NKV*HD);
        splitT_kernel<<<dim3((NKV*HD)/32, HID/32), dim3(32,8)>>>(wv, wvh, wvl, HID, NKV*HD);
        splitT_kernel<<<dim3(HID/32, HID/32), dim3(32,8)>>>(wo, woh, wol, HID, HID);
    }

    // QKV projections (tensor cores, 3-term bf16)
    gemm3_kernel<<<dim3((NH*HD)/128, MROWS/128), 256, GSMEM_BYTES>>>(
        xhi, xlo, wqh, wql, q, MROWS, NH*HD, HID);
    gemm3_kernel<<<dim3((NKV*HD)/128, MROWS/128), 256, GSMEM_BYTES>>>(
        xhi, xlo, wkh, wkl, k, MROWS, NKV*HD, HID);
    gemm3_kernel<<<dim3((NKV*HD)/128, MROWS/128), 256, GSMEM_BYTES>>>(
        xhi, xlo, wvh, wvl, v, MROWS, NKV*HD, HID);

    // RoPE + prescale + split to bf16 hi/lo; V plain split
    {
        const float qscale = 0.08838834764831845f * 1.4426950408889634f; // 1/sqrt(128)*log2e
        int pq = MROWS * NH * 64;
        int pk = MROWS * NKV * 64;
        rope_split_kernel<<<(pq + 255) / 256, 256>>>(q, qh, ql, fcos, fsin, NH, qscale, pq);
        rope_split_kernel<<<(pk + 255) / 256, 256>>>(k, kh, kl, fcos, fsin, NKV, 1.0f, pk);
        int n4 = MROWS * NKV * HD / 4;
        split_kernel<<<(n4 + 255) / 256, 256>>>((const float4*)v,
                                                (ushort4*)vh, (ushort4*)vl, n4);
    }

    // Flash attention (HMMA)
    flash_mma_kernel<<<dim3(SEQ / 128, NH, BATCH), 256, FSMEM>>>(
        qh, ql, kh, kl, vh, vl, attn);

    // Output projection
    {
        int n4 = MROWS * HID / 4;
        split_kernel<<<(n4 + 255) / 256, 256>>>((const float4*)attn,
                                                (ushort4*)ahi, (ushort4*)alo, n4);
        gemm3_kernel<<<dim3(HID/128, MROWS/128), 256, GSMEM_BYTES>>>(
            ahi, alo, woh, wol, out, MROWS, HID, HID);
    }
}